// round 12
// baseline (speedup 1.0000x reference)
#include <cuda_runtime.h>
#include <cuda_bf16.h>
#include <cuda_fp8.h>
#include <math.h>
#include <stdint.h>

#define BATCH 1024
#define FEAT  2048
#define NCLS  11003
#define NPAD  11008
#define NT1   172           // N tiles of 64 for gemm1
#define NCH   344           // 32-col LSE chunks (NPAD/32)
#define ROWS2 2048          // stacked [v; t]

#define ASCALE 64.0f
#define WSCALE 4.0f

#define WT_BLOCKS (344 * 16)            // wtrans sub-grid
#define G1_BLOCKS (NT1 * 16)            // 2752
#define G2_BLOCKS 256                   // gemm2 64x64 tiles (16 m x 16 n)
#define TOT_BLOCKS (G1_BLOCKS + G2_BLOCKS)
#define NFIN 8                          // finisher (combine) blocks

// ---------------- device scratch (static, no runtime alloc) ----------------
__device__ __align__(128) __nv_bfloat16 g_abuf[ROWS2 * FEAT];   // normalized [v;t] bf16
__device__ __align__(128) uint8_t g_a8[(size_t)ROWS2 * FEAT];   // fp8 v-hat * 64
__device__ __align__(128) uint8_t g_w8t[(size_t)NPAD * FEAT];   // fp8 W^T [n][k] * 4
__device__ float g_colsqp[16 * NPAD];
__device__ float g_ll[ROWS2];
__device__ float g_pmax[NCH * ROWS2];
__device__ float g_psum[NCH * ROWS2];
__device__ float g_gal_part[G2_BLOCKS];
__device__ float g_inst_part[NFIN];
__device__ int   g_lab[BATCH];
__device__ int   g_ctr;                 // zero-init; self-resetting tickets
__device__ int   g_ctr2;

__device__ __forceinline__ uint8_t to_e4m3(float x) {
    __nv_fp8_e4m3 v(x);
    return *reinterpret_cast<uint8_t*>(&v);
}

// ======================= prep_fused: wtrans + normalize =======================
__global__ void prep_fused_kernel(const float* __restrict__ W,
                                  const float* __restrict__ vis,
                                  const float* __restrict__ txt,
                                  const int* __restrict__ lb) {
    __shared__ float s[128][33];
    __shared__ float sq[8][33];
    int bid = blockIdx.x;
    int t = threadIdx.x;

    if (bid < WT_BLOCKS) {
        // ---- wtrans: W -> fp8 [n][k] + colsq partials ----
        int tx = t & 31, ty = t >> 5;
        int c0 = (bid % 344) * 32, k0 = (bid / 344) * 128;
        int c = c0 + tx;
        float p = 0.f;
        #pragma unroll
        for (int i = 0; i < 16; i++) {
            int k = k0 + ty + 8 * i;
            float w = (c < NCLS) ? W[(size_t)k * NCLS + c] : 0.f;
            s[ty + 8 * i][tx] = w;
            p += w * w;
        }
        sq[ty][tx] = p;
        __syncthreads();
        if (ty == 0) {
            float ssum = 0.f;
            #pragma unroll
            for (int i = 0; i < 8; i++) ssum += sq[i][tx];
            g_colsqp[(bid / 344) * NPAD + c] = ssum;
        }
        #pragma unroll
        for (int j = 0; j < 4; j++) {
            int nl = ty + 8 * j;
            int kq = tx;
            uchar4 pk = make_uchar4(to_e4m3(s[4*kq+0][nl] * WSCALE),
                                    to_e4m3(s[4*kq+1][nl] * WSCALE),
                                    to_e4m3(s[4*kq+2][nl] * WSCALE),
                                    to_e4m3(s[4*kq+3][nl] * WSCALE));
            *(uint32_t*)(g_w8t + (size_t)(c0 + nl) * FEAT + k0 + 4 * kq) =
                *reinterpret_cast<uint32_t*>(&pk);
        }
    } else {
        // ---- normalize row r + labels (block WT_BLOCKS handles labels) ----
        int r = bid - WT_BLOCKS;        // 0..2047
        if (r == 0) {
            bool is64 = true;
            #pragma unroll
            for (int j = 1; j < 64; j += 2)
                if (lb[j] != 0) is64 = false;
            #pragma unroll
            for (int i = 0; i < 4; i++) {
                int idx = t + 256 * i;
                g_lab[idx] = is64 ? lb[2 * idx] : lb[idx];
            }
        }
        const float* src = (r < BATCH) ? (vis + (size_t)r * FEAT)
                                       : (txt + (size_t)(r - BATCH) * FEAT);
        float4 x0 = ((const float4*)src)[t];
        float4 x1 = ((const float4*)src)[t + 256];
        float ss = x0.x*x0.x + x0.y*x0.y + x0.z*x0.z + x0.w*x0.w
                 + x1.x*x1.x + x1.y*x1.y + x1.z*x1.z + x1.w*x1.w;
        #pragma unroll
        for (int o = 16; o > 0; o >>= 1) ss += __shfl_xor_sync(0xffffffffu, ss, o);
        float* ws = &sq[0][0];
        if ((t & 31) == 0) ws[t >> 5] = ss;
        __syncthreads();
        if (t == 0) {
            float sum = 0.f;
            #pragma unroll
            for (int i = 0; i < 8; i++) sum += ws[i];
            ws[8] = rsqrtf(sum);
        }
        __syncthreads();
        float rn = ws[8];
        __nv_bfloat162* dst = (__nv_bfloat162*)(g_abuf + (size_t)r * FEAT);
        dst[2*t]       = __nv_bfloat162(__float2bfloat16(x0.x*rn), __float2bfloat16(x0.y*rn));
        dst[2*t + 1]   = __nv_bfloat162(__float2bfloat16(x0.z*rn), __float2bfloat16(x0.w*rn));
        dst[512 + 2*t]     = __nv_bfloat162(__float2bfloat16(x1.x*rn), __float2bfloat16(x1.y*rn));
        dst[512 + 2*t + 1] = __nv_bfloat162(__float2bfloat16(x1.z*rn), __float2bfloat16(x1.w*rn));

        float fa = rn * ASCALE;
        uchar4 p0 = make_uchar4(to_e4m3(x0.x*fa), to_e4m3(x0.y*fa),
                                to_e4m3(x0.z*fa), to_e4m3(x0.w*fa));
        uchar4 p1 = make_uchar4(to_e4m3(x1.x*fa), to_e4m3(x1.y*fa),
                                to_e4m3(x1.z*fa), to_e4m3(x1.w*fa));
        uint32_t* d8 = (uint32_t*)(g_a8 + (size_t)r * FEAT);
        d8[t]       = *reinterpret_cast<uint32_t*>(&p0);
        d8[t + 256] = *reinterpret_cast<uint32_t*>(&p1);
    }
}

// ---------------- mma helpers ----------------
__device__ __forceinline__ void ldmx4(uint32_t* r, uint32_t a) {
    asm volatile("ldmatrix.sync.aligned.m8n8.x4.shared.b16 {%0,%1,%2,%3},[%4];\n"
                 : "=r"(r[0]), "=r"(r[1]), "=r"(r[2]), "=r"(r[3]) : "r"(a));
}
__device__ __forceinline__ void mma16816(float* c, const uint32_t* a, const uint32_t* b) {
    asm volatile("mma.sync.aligned.m16n8k16.row.col.f32.bf16.bf16.f32 "
                 "{%0,%1,%2,%3},{%4,%5,%6,%7},{%8,%9},{%0,%1,%2,%3};\n"
                 : "+f"(c[0]), "+f"(c[1]), "+f"(c[2]), "+f"(c[3])
                 : "r"(a[0]), "r"(a[1]), "r"(a[2]), "r"(a[3]),
                   "r"(b[0]), "r"(b[1]));
}
__device__ __forceinline__ void mma16832f8(float* c, const uint32_t* a, const uint32_t* b) {
    asm volatile("mma.sync.aligned.m16n8k32.row.col.f32.e4m3.e4m3.f32 "
                 "{%0,%1,%2,%3},{%4,%5,%6,%7},{%8,%9},{%0,%1,%2,%3};\n"
                 : "+f"(c[0]), "+f"(c[1]), "+f"(c[2]), "+f"(c[3])
                 : "r"(a[0]), "r"(a[1]), "r"(a[2]), "r"(a[3]),
                   "r"(b[0]), "r"(b[1]));
}
__device__ __forceinline__ void cpa16(uint32_t dst, const void* src) {
    asm volatile("cp.async.cg.shared.global [%0], [%1], 16;" :: "r"(dst), "l"(src));
}
__device__ __forceinline__ void cpa_commit() {
    asm volatile("cp.async.commit_group;" ::: "memory");
}
template <int N> __device__ __forceinline__ void cpa_wait() {
    asm volatile("cp.async.wait_group %0;" :: "n"(N) : "memory");
}

// ======================= gemm_fused (+in-kernel combine/finalize) ============
// blocks [0, G1_BLOCKS): gemm1 fp8 128x64x128B (unchanged core)
// blocks [G1_BLOCKS, +G2_BLOCKS): gemm2 bf16 64x64 (fills gemm1's tail wave)
// blocks [G1_BLOCKS, +NFIN): additionally run combine+finalize after a
//   grid-completion ticket (all 3008 blocks fenced+counted).
#define F8_AB   (128 * 128)             // 16384
#define F8_BB   (64 * 128)              // 8192
#define F8_STG  (F8_AB + F8_BB)         // 24576
#define G1_SMEM (3 * F8_STG)            // 73728
#define G1_NSTG 16
#define G2_NSTG 32

__global__ __launch_bounds__(256, 3) void gemm_fused_kernel(float* __restrict__ out) {
    extern __shared__ char smem[];
    __shared__ float sInv[64];
    int tid = threadIdx.x, warp = tid >> 5, lane = tid & 31;
    uint32_t sb = (uint32_t)__cvta_generic_to_shared(smem);
    int arow = tid >> 3, q = tid & 7;
    uint32_t asw = (uint32_t)((q ^ (arow & 7)) << 4);

    if (blockIdx.x < G1_BLOCKS) {
        // ================= gemm1: fp8 logits + LSE =================
        int ntile = blockIdx.x % NT1, mtile = blockIdx.x / NT1;
        int wm = warp & 3, wn = warp >> 2;
        float c[2][4][4];
        #pragma unroll
        for (int mf = 0; mf < 2; mf++)
            #pragma unroll
            for (int nf = 0; nf < 4; nf++)
                #pragma unroll
                for (int j = 0; j < 4; j++) c[mf][nf][j] = 0.f;

        uint32_t adst0 = (uint32_t)(arow * 128) + asw;
        const uint8_t* asrc0 = g_a8 + ((size_t)(mtile * 128 + arow)) * FEAT + q * 16;
        uint32_t bdst0 = (uint32_t)F8_AB + (uint32_t)(arow * 128) + asw;
        const uint8_t* bsrc0 = g_w8t + ((size_t)(ntile * 64 + arow)) * FEAT + q * 16;

        int koff = 0;
        auto issue_stage = [&](uint32_t bufbase) {
            #pragma unroll
            for (int i = 0; i < 4; i++)
                cpa16(bufbase + adst0 + i * 4096, asrc0 + (size_t)i * 32 * FEAT + koff);
            #pragma unroll
            for (int i = 0; i < 2; i++)
                cpa16(bufbase + bdst0 + i * 4096, bsrc0 + (size_t)i * 32 * FEAT + koff);
            cpa_commit();
            koff += 128;
        };

        int arow0 = wm * 32 + (lane & 15);
        int brow0 = wn * 32 + (lane & 7) + ((lane >> 4) << 3);
        int ahi = lane >> 4, bhi = (lane >> 3) & 1;
        uint32_t aoff = (uint32_t)(arow0 * 128);
        uint32_t boff = (uint32_t)F8_AB + (uint32_t)(brow0 * 128);
        uint32_t colA[4], colB[4];
        #pragma unroll
        for (int ks = 0; ks < 4; ks++) {
            colA[ks] = (uint32_t)(((ks * 2 + ahi) ^ (arow0 & 7)) << 4);
            colB[ks] = (uint32_t)(((ks * 2 + bhi) ^ (brow0 & 7)) << 4);
        }

        issue_stage(sb);
        issue_stage(sb + F8_STG);

        if (tid < 64) {
            int cidx = ntile * 64 + tid;
            float s = 0.f;
            #pragma unroll
            for (int i = 0; i < 16; i++) s += g_colsqp[i * NPAD + cidx];
            sInv[tid] = (cidx < NCLS) ? (28.0f / (ASCALE * WSCALE)) * rsqrtf(s) : 0.f;
        }

        for (int kt = 0; kt < G1_NSTG; kt++) {
            uint32_t bufbase = sb + (kt % 3) * F8_STG;
            if (kt < G1_NSTG - 1) cpa_wait<1>(); else cpa_wait<0>();
            __syncthreads();
            if (kt + 2 < G1_NSTG) issue_stage(sb + ((kt + 2) % 3) * F8_STG);

            uint32_t abase = bufbase + aoff;
            uint32_t bbase = bufbase + boff;
            #pragma unroll
            for (int ks = 0; ks < 4; ks++) {
                uint32_t a[2][4], b[4][2];
                ldmx4(a[0], abase + colA[ks]);
                ldmx4(a[1], abase + 2048 + colA[ks]);
                {
                    uint32_t r[4];
                    ldmx4(r, bbase + colB[ks]);
                    b[0][0] = r[0]; b[0][1] = r[1];
                    b[1][0] = r[2]; b[1][1] = r[3];
                    ldmx4(r, bbase + 2048 + colB[ks]);
                    b[2][0] = r[0]; b[2][1] = r[1];
                    b[3][0] = r[2]; b[3][1] = r[3];
                }
                #pragma unroll
                for (int mf = 0; mf < 2; mf++)
                    #pragma unroll
                    for (int nf = 0; nf < 4; nf++)
                        mma16832f8(c[mf][nf], a[mf], b[nf]);
            }
        }

        int g = lane >> 2, tg = lane & 3;
        #pragma unroll
        for (int mf = 0; mf < 2; mf++)
            #pragma unroll
            for (int pr = 0; pr < 2; pr++) {
                int R = mtile * 128 + wm * 32 + mf * 16 + pr * 8 + g;
                int lbl = g_lab[R & (BATCH - 1)];
                float v[8];
                float mx = -1e30f;
                #pragma unroll
                for (int nf = 0; nf < 4; nf++)
                    #pragma unroll
                    for (int j = 0; j < 2; j++) {
                        int nl = wn * 32 + nf * 8 + tg * 2 + j;
                        int n = ntile * 64 + nl;
                        float val = c[mf][nf][pr * 2 + j] * sInv[nl];
                        if (n >= NCLS) val = -1e30f;
                        if (n == lbl) g_ll[R] = val;
                        v[nf * 2 + j] = val;
                        mx = fmaxf(mx, val);
                    }
                mx = fmaxf(mx, __shfl_xor_sync(0xffffffffu, mx, 1));
                mx = fmaxf(mx, __shfl_xor_sync(0xffffffffu, mx, 2));
                float s = 0.f;
                #pragma unroll
                for (int i = 0; i < 8; i++) s += __expf(v[i] - mx);
                s += __shfl_xor_sync(0xffffffffu, s, 1);
                s += __shfl_xor_sync(0xffffffffu, s, 2);
                if (tg == 0) {
                    int chunk = ntile * 2 + wn;
                    g_pmax[chunk * ROWS2 + R] = mx;
                    g_psum[chunk * ROWS2 + R] = s;
                }
            }
        // publish partials
        __threadfence();
        __syncthreads();
        if (tid == 0) atomicAdd(&g_ctr, 1);
    } else {
        // ================= gemm2: bf16 sim + soft-margin =================
        int bid2 = blockIdx.x - G1_BLOCKS;
        int ntile2 = bid2 & 15, mtile2 = bid2 >> 4;   // 16 x 16
        int wm = warp & 1, wn = warp >> 1;            // 2 x 4 warps
        float c[2][2][4];
        #pragma unroll
        for (int mf = 0; mf < 2; mf++)
            #pragma unroll
            for (int nf = 0; nf < 2; nf++)
                #pragma unroll
                for (int j = 0; j < 4; j++) c[mf][nf][j] = 0.f;

        const uint8_t* ab8 = (const uint8_t*)g_abuf;
        uint32_t adst0 = (uint32_t)(arow * 128) + asw;
        const uint8_t* asrc0 = ab8 + ((size_t)(mtile2 * 64 + arow)) * (FEAT * 2) + q * 16;
        uint32_t bdst0 = (uint32_t)F8_BB + (uint32_t)(arow * 128) + asw;
        const uint8_t* bsrc0 = ab8 + ((size_t)(BATCH + ntile2 * 64 + arow)) * (FEAT * 2) + q * 16;

        int koff = 0;
        auto issue_stage2 = [&](uint32_t bufbase) {
            #pragma unroll
            for (int i = 0; i < 2; i++)
                cpa16(bufbase + adst0 + i * 4096, asrc0 + (size_t)i * 32 * (FEAT * 2) + koff);
            #pragma unroll
            for (int i = 0; i < 2; i++)
                cpa16(bufbase + bdst0 + i * 4096, bsrc0 + (size_t)i * 32 * (FEAT * 2) + koff);
            cpa_commit();
            koff += 128;
        };

        int arow0 = wm * 32 + (lane & 15);
        int brow0 = wn * 16 + (lane & 7) + ((lane >> 4) << 3);
        int ahi = lane >> 4, bhi = (lane >> 3) & 1;
        uint32_t aoff = (uint32_t)(arow0 * 128);
        uint32_t boff = (uint32_t)F8_BB + (uint32_t)(brow0 * 128);
        uint32_t colA[4], colB[4];
        #pragma unroll
        for (int ks = 0; ks < 4; ks++) {
            colA[ks] = (uint32_t)(((ks * 2 + ahi) ^ (arow0 & 7)) << 4);
            colB[ks] = (uint32_t)(((ks * 2 + bhi) ^ (brow0 & 7)) << 4);
        }

        issue_stage2(sb);
        issue_stage2(sb + F8_STG);

        for (int kt = 0; kt < G2_NSTG; kt++) {
            uint32_t bufbase = sb + (kt % 3) * F8_STG;
            if (kt < G2_NSTG - 1) cpa_wait<1>(); else cpa_wait<0>();
            __syncthreads();
            if (kt + 2 < G2_NSTG) issue_stage2(sb + ((kt + 2) % 3) * F8_STG);

            uint32_t abase = bufbase + aoff;
            uint32_t bbase = bufbase + boff;
            #pragma unroll
            for (int ks = 0; ks < 4; ks++) {
                uint32_t a[2][4], b[2][2];
                ldmx4(a[0], abase + colA[ks]);
                ldmx4(a[1], abase + 2048 + colA[ks]);
                {
                    uint32_t r[4];
                    ldmx4(r, bbase + colB[ks]);
                    b[0][0] = r[0]; b[0][1] = r[1];
                    b[1][0] = r[2]; b[1][1] = r[3];
                }
                #pragma unroll
                for (int mf = 0; mf < 2; mf++)
                    #pragma unroll
                    for (int nf = 0; nf < 2; nf++)
                        mma16816(c[mf][nf], a[mf], b[nf]);
            }
        }

        int g = lane >> 2, tg = lane & 3;
        float local = 0.f;
        #pragma unroll
        for (int mf = 0; mf < 2; mf++)
            #pragma unroll
            for (int pr = 0; pr < 2; pr++) {
                int R = mtile2 * 64 + wm * 32 + mf * 16 + pr * 8 + g;
                int lr = g_lab[R];
                #pragma unroll
                for (int nf = 0; nf < 2; nf++)
                    #pragma unroll
                    for (int j = 0; j < 2; j++) {
                        int n = ntile2 * 64 + wn * 16 + nf * 8 + tg * 2 + j;
                        int lc = g_lab[n];
                        float s = c[mf][nf][pr * 2 + j];
                        float x = (lr == lc) ? (-10.f * (s - 0.6f))
                                             : (40.f * (s - 0.4f));
                        local += (x > 15.f) ? x : log1pf(__expf(x));
                    }
            }
        #pragma unroll
        for (int o = 16; o > 0; o >>= 1) local += __shfl_xor_sync(0xffffffffu, local, o);
        if (lane == 0) sInv[warp] = local;      // reuse sInv as scratch
        __syncthreads();
        if (tid == 0) {
            float t2 = 0.f;
            #pragma unroll
            for (int i = 0; i < 8; i++) t2 += sInv[i];
            g_gal_part[bid2] = t2;
        }
        // publish partials
        __threadfence();
        __syncthreads();
        if (tid == 0) atomicAdd(&g_ctr, 1);

        // ===== finisher blocks: combine + finalize after ALL blocks done =====
        if (bid2 < NFIN) {
            if (tid == 0) {
                while (*(volatile int*)&g_ctr < TOT_BLOCKS) { }
            }
            __syncthreads();
            __threadfence();   // acquire: make all partials visible

            int r = bid2 * 256 + tid;          // 8 x 256 = 2048 rows
            float mx = -1e30f;
            #pragma unroll 8
            for (int i = 0; i < NCH; i++) mx = fmaxf(mx, g_pmax[i * ROWS2 + r]);
            float s = 0.f;
            #pragma unroll 8
            for (int i = 0; i < NCH; i++)
                s += g_psum[i * ROWS2 + r] * __expf(g_pmax[i * ROWS2 + r] - mx);
            float contrib = mx + logf(s) - g_ll[r];

            #pragma unroll
            for (int o = 16; o > 0; o >>= 1)
                contrib += __shfl_xor_sync(0xffffffffu, contrib, o);
            if (lane == 0) sInv[warp] = contrib;
            __syncthreads();
            if (tid == 0) {
                float bi = 0.f;
                #pragma unroll
                for (int i = 0; i < 8; i++) bi += sInv[i];
                g_inst_part[bid2] = bi;
                __threadfence();
                int t2 = atomicAdd(&g_ctr2, 1);
                if (t2 == NFIN - 1) {
                    // last finisher: fixed-order final sums
                    float si = 0.f;
                    for (int i = 0; i < NFIN; i++) si += g_inst_part[i];
                    float sg = 0.f;
                    for (int i = 0; i < G2_BLOCKS; i++) sg += g_gal_part[i];
                    out[0] = si * (1.0f / BATCH);
                    out[1] = 2.0f * sg / BATCH;
                    g_ctr = 0;      // reset for next graph replay
                    g_ctr2 = 0;
                }
            }
        }
    }
}

// ---------------- launch: 2 kernels, one stream ----------------
extern "C" void kernel_launch(void* const* d_in, const int* in_sizes, int n_in,
                              void* d_out, int out_size) {
    const float* vis = (const float*)d_in[0];
    const float* txt = (const float*)d_in[1];
    const int* lab = (const int*)d_in[2];
    const float* W = (const float*)d_in[3];
    float* out = (float*)d_out;

    cudaFuncSetAttribute(gemm_fused_kernel,
                         cudaFuncAttributeMaxDynamicSharedMemorySize, G1_SMEM);

    prep_fused_kernel<<<WT_BLOCKS + ROWS2, 256>>>(W, vis, txt, lab);
    gemm_fused_kernel<<<TOT_BLOCKS, 256, G1_SMEM>>>(out);
}

// round 13
// speedup vs baseline: 1.0015x; 1.0015x over previous
#include <cuda_runtime.h>
#include <cuda_bf16.h>
#include <cuda_fp8.h>
#include <math.h>
#include <stdint.h>

#define BATCH 1024
#define FEAT  2048
#define NCLS  11003
#define NPAD  11008
#define NT1   172           // N tiles of 64 for gemm1
#define NCH   344           // 32-col LSE chunks (NPAD/32)
#define ROWS2 2048          // stacked [v; t]

#define ASCALE 64.0f
#define WSCALE 4.0f

#define WT_BLOCKS (344 * 16)            // wtrans sub-grid
#define G1_BLOCKS (NT1 * 16)            // 2752
#define G2_BLOCKS 256                   // gemm2 64x64 tiles (16 m x 16 n)

// ---------------- device scratch (static, no runtime alloc) ----------------
__device__ __align__(128) __nv_bfloat16 g_abuf[ROWS2 * FEAT];   // normalized [v;t] bf16
__device__ __align__(128) uint8_t g_a8[(size_t)ROWS2 * FEAT];   // fp8 v-hat * 64
__device__ __align__(128) uint8_t g_w8t[(size_t)NPAD * FEAT];   // fp8 W^T [n][k] * 4
__device__ float g_colsqp[16 * NPAD];
__device__ float g_ll[ROWS2];
__device__ float g_pmax[NCH * ROWS2];
__device__ float g_psum[NCH * ROWS2];
__device__ float g_gal_part[G2_BLOCKS];
__device__ float g_inst_part[32];
__device__ int   g_lab[BATCH];
__device__ int   g_ctr;                 // zero-init; self-resetting ticket

__device__ __forceinline__ uint8_t to_e4m3(float x) {
    __nv_fp8_e4m3 v(x);
    return *reinterpret_cast<uint8_t*>(&v);
}

// ======================= prep_fused: wtrans + normalize =======================
__global__ void prep_fused_kernel(const float* __restrict__ W,
                                  const float* __restrict__ vis,
                                  const float* __restrict__ txt,
                                  const int* __restrict__ lb) {
    __shared__ float s[128][33];
    __shared__ float sq[8][33];
    int bid = blockIdx.x;
    int t = threadIdx.x;

    if (bid < WT_BLOCKS) {
        // ---- wtrans: W -> fp8 [n][k] + colsq partials ----
        int tx = t & 31, ty = t >> 5;
        int c0 = (bid % 344) * 32, k0 = (bid / 344) * 128;
        int c = c0 + tx;
        float p = 0.f;
        #pragma unroll
        for (int i = 0; i < 16; i++) {
            int k = k0 + ty + 8 * i;
            float w = (c < NCLS) ? W[(size_t)k * NCLS + c] : 0.f;
            s[ty + 8 * i][tx] = w;
            p += w * w;
        }
        sq[ty][tx] = p;
        __syncthreads();
        if (ty == 0) {
            float ssum = 0.f;
            #pragma unroll
            for (int i = 0; i < 8; i++) ssum += sq[i][tx];
            g_colsqp[(bid / 344) * NPAD + c] = ssum;
        }
        #pragma unroll
        for (int j = 0; j < 4; j++) {
            int nl = ty + 8 * j;
            int kq = tx;
            uchar4 pk = make_uchar4(to_e4m3(s[4*kq+0][nl] * WSCALE),
                                    to_e4m3(s[4*kq+1][nl] * WSCALE),
                                    to_e4m3(s[4*kq+2][nl] * WSCALE),
                                    to_e4m3(s[4*kq+3][nl] * WSCALE));
            *(uint32_t*)(g_w8t + (size_t)(c0 + nl) * FEAT + k0 + 4 * kq) =
                *reinterpret_cast<uint32_t*>(&pk);
        }
    } else {
        // ---- normalize row r + labels (block WT_BLOCKS handles labels) ----
        int r = bid - WT_BLOCKS;        // 0..2047
        if (r == 0) {
            bool is64 = true;
            #pragma unroll
            for (int j = 1; j < 64; j += 2)
                if (lb[j] != 0) is64 = false;
            #pragma unroll
            for (int i = 0; i < 4; i++) {
                int idx = t + 256 * i;
                g_lab[idx] = is64 ? lb[2 * idx] : lb[idx];
            }
        }
        const float* src = (r < BATCH) ? (vis + (size_t)r * FEAT)
                                       : (txt + (size_t)(r - BATCH) * FEAT);
        float4 x0 = ((const float4*)src)[t];
        float4 x1 = ((const float4*)src)[t + 256];
        float ss = x0.x*x0.x + x0.y*x0.y + x0.z*x0.z + x0.w*x0.w
                 + x1.x*x1.x + x1.y*x1.y + x1.z*x1.z + x1.w*x1.w;
        #pragma unroll
        for (int o = 16; o > 0; o >>= 1) ss += __shfl_xor_sync(0xffffffffu, ss, o);
        float* ws = &sq[0][0];
        if ((t & 31) == 0) ws[t >> 5] = ss;
        __syncthreads();
        if (t == 0) {
            float sum = 0.f;
            #pragma unroll
            for (int i = 0; i < 8; i++) sum += ws[i];
            ws[8] = rsqrtf(sum);
        }
        __syncthreads();
        float rn = ws[8];
        __nv_bfloat162* dst = (__nv_bfloat162*)(g_abuf + (size_t)r * FEAT);
        dst[2*t]       = __nv_bfloat162(__float2bfloat16(x0.x*rn), __float2bfloat16(x0.y*rn));
        dst[2*t + 1]   = __nv_bfloat162(__float2bfloat16(x0.z*rn), __float2bfloat16(x0.w*rn));
        dst[512 + 2*t]     = __nv_bfloat162(__float2bfloat16(x1.x*rn), __float2bfloat16(x1.y*rn));
        dst[512 + 2*t + 1] = __nv_bfloat162(__float2bfloat16(x1.z*rn), __float2bfloat16(x1.w*rn));

        float fa = rn * ASCALE;
        uchar4 p0 = make_uchar4(to_e4m3(x0.x*fa), to_e4m3(x0.y*fa),
                                to_e4m3(x0.z*fa), to_e4m3(x0.w*fa));
        uchar4 p1 = make_uchar4(to_e4m3(x1.x*fa), to_e4m3(x1.y*fa),
                                to_e4m3(x1.z*fa), to_e4m3(x1.w*fa));
        uint32_t* d8 = (uint32_t*)(g_a8 + (size_t)r * FEAT);
        d8[t]       = *reinterpret_cast<uint32_t*>(&p0);
        d8[t + 256] = *reinterpret_cast<uint32_t*>(&p1);
    }
}

// ---------------- mma helpers ----------------
__device__ __forceinline__ void ldmx4(uint32_t* r, uint32_t a) {
    asm volatile("ldmatrix.sync.aligned.m8n8.x4.shared.b16 {%0,%1,%2,%3},[%4];\n"
                 : "=r"(r[0]), "=r"(r[1]), "=r"(r[2]), "=r"(r[3]) : "r"(a));
}
__device__ __forceinline__ void mma16816(float* c, const uint32_t* a, const uint32_t* b) {
    asm volatile("mma.sync.aligned.m16n8k16.row.col.f32.bf16.bf16.f32 "
                 "{%0,%1,%2,%3},{%4,%5,%6,%7},{%8,%9},{%0,%1,%2,%3};\n"
                 : "+f"(c[0]), "+f"(c[1]), "+f"(c[2]), "+f"(c[3])
                 : "r"(a[0]), "r"(a[1]), "r"(a[2]), "r"(a[3]),
                   "r"(b[0]), "r"(b[1]));
}
__device__ __forceinline__ void mma16832f8(float* c, const uint32_t* a, const uint32_t* b) {
    asm volatile("mma.sync.aligned.m16n8k32.row.col.f32.e4m3.e4m3.f32 "
                 "{%0,%1,%2,%3},{%4,%5,%6,%7},{%8,%9},{%0,%1,%2,%3};\n"
                 : "+f"(c[0]), "+f"(c[1]), "+f"(c[2]), "+f"(c[3])
                 : "r"(a[0]), "r"(a[1]), "r"(a[2]), "r"(a[3]),
                   "r"(b[0]), "r"(b[1]));
}
__device__ __forceinline__ void cpa16(uint32_t dst, const void* src) {
    asm volatile("cp.async.cg.shared.global [%0], [%1], 16;" :: "r"(dst), "l"(src));
}
__device__ __forceinline__ void cpa_commit() {
    asm volatile("cp.async.commit_group;" ::: "memory");
}
template <int N> __device__ __forceinline__ void cpa_wait() {
    asm volatile("cp.async.wait_group %0;" :: "n"(N) : "memory");
}

// ======================= gemm_fused =======================
// blocks [0, G2_BLOCKS): gemm2 bf16 64x64 (longer CTAs -> wave 0, not tail)
// blocks [G2_BLOCKS, +G1_BLOCKS): gemm1 fp8 128x64x128B (ceiling-bound core)
#define F8_AB   (128 * 128)             // 16384
#define F8_BB   (64 * 128)              // 8192
#define F8_STG  (F8_AB + F8_BB)         // 24576
#define G1_SMEM (3 * F8_STG)            // 73728
#define G1_NSTG 16
#define G2_NSTG 32

__global__ __launch_bounds__(256, 3) void gemm_fused_kernel() {
    extern __shared__ char smem[];
    __shared__ float sInv[64];
    int tid = threadIdx.x, warp = tid >> 5, lane = tid & 31;
    uint32_t sb = (uint32_t)__cvta_generic_to_shared(smem);
    int arow = tid >> 3, q = tid & 7;
    uint32_t asw = (uint32_t)((q ^ (arow & 7)) << 4);

    if (blockIdx.x >= G2_BLOCKS) {
        // ================= gemm1: fp8 logits + LSE =================
        int bid1 = blockIdx.x - G2_BLOCKS;
        int ntile = bid1 % NT1, mtile = bid1 / NT1;
        int wm = warp & 3, wn = warp >> 2;
        float c[2][4][4];
        #pragma unroll
        for (int mf = 0; mf < 2; mf++)
            #pragma unroll
            for (int nf = 0; nf < 4; nf++)
                #pragma unroll
                for (int j = 0; j < 4; j++) c[mf][nf][j] = 0.f;

        uint32_t adst0 = (uint32_t)(arow * 128) + asw;
        const uint8_t* asrc0 = g_a8 + ((size_t)(mtile * 128 + arow)) * FEAT + q * 16;
        uint32_t bdst0 = (uint32_t)F8_AB + (uint32_t)(arow * 128) + asw;
        const uint8_t* bsrc0 = g_w8t + ((size_t)(ntile * 64 + arow)) * FEAT + q * 16;

        int koff = 0;
        auto issue_stage = [&](uint32_t bufbase) {
            #pragma unroll
            for (int i = 0; i < 4; i++)
                cpa16(bufbase + adst0 + i * 4096, asrc0 + (size_t)i * 32 * FEAT + koff);
            #pragma unroll
            for (int i = 0; i < 2; i++)
                cpa16(bufbase + bdst0 + i * 4096, bsrc0 + (size_t)i * 32 * FEAT + koff);
            cpa_commit();
            koff += 128;
        };

        int arow0 = wm * 32 + (lane & 15);
        int brow0 = wn * 32 + (lane & 7) + ((lane >> 4) << 3);
        int ahi = lane >> 4, bhi = (lane >> 3) & 1;
        uint32_t aoff = (uint32_t)(arow0 * 128);
        uint32_t boff = (uint32_t)F8_AB + (uint32_t)(brow0 * 128);
        uint32_t colA[4], colB[4];
        #pragma unroll
        for (int ks = 0; ks < 4; ks++) {
            colA[ks] = (uint32_t)(((ks * 2 + ahi) ^ (arow0 & 7)) << 4);
            colB[ks] = (uint32_t)(((ks * 2 + bhi) ^ (brow0 & 7)) << 4);
        }

        issue_stage(sb);
        issue_stage(sb + F8_STG);

        if (tid < 64) {
            int cidx = ntile * 64 + tid;
            float s = 0.f;
            #pragma unroll
            for (int i = 0; i < 16; i++) s += g_colsqp[i * NPAD + cidx];
            sInv[tid] = (cidx < NCLS) ? (28.0f / (ASCALE * WSCALE)) * rsqrtf(s) : 0.f;
        }

        for (int kt = 0; kt < G1_NSTG; kt++) {
            uint32_t bufbase = sb + (kt % 3) * F8_STG;
            if (kt < G1_NSTG - 1) cpa_wait<1>(); else cpa_wait<0>();
            __syncthreads();
            if (kt + 2 < G1_NSTG) issue_stage(sb + ((kt + 2) % 3) * F8_STG);

            uint32_t abase = bufbase + aoff;
            uint32_t bbase = bufbase + boff;
            #pragma unroll
            for (int ks = 0; ks < 4; ks++) {
                uint32_t a[2][4], b[4][2];
                ldmx4(a[0], abase + colA[ks]);
                ldmx4(a[1], abase + 2048 + colA[ks]);
                {
                    uint32_t r[4];
                    ldmx4(r, bbase + colB[ks]);
                    b[0][0] = r[0]; b[0][1] = r[1];
                    b[1][0] = r[2]; b[1][1] = r[3];
                    ldmx4(r, bbase + 2048 + colB[ks]);
                    b[2][0] = r[0]; b[2][1] = r[1];
                    b[3][0] = r[2]; b[3][1] = r[3];
                }
                #pragma unroll
                for (int mf = 0; mf < 2; mf++)
                    #pragma unroll
                    for (int nf = 0; nf < 4; nf++)
                        mma16832f8(c[mf][nf], a[mf], b[nf]);
            }
        }

        int g = lane >> 2, tg = lane & 3;
        #pragma unroll
        for (int mf = 0; mf < 2; mf++)
            #pragma unroll
            for (int pr = 0; pr < 2; pr++) {
                int R = mtile * 128 + wm * 32 + mf * 16 + pr * 8 + g;
                int lbl = g_lab[R & (BATCH - 1)];
                float v[8];
                float mx = -1e30f;
                #pragma unroll
                for (int nf = 0; nf < 4; nf++)
                    #pragma unroll
                    for (int j = 0; j < 2; j++) {
                        int nl = wn * 32 + nf * 8 + tg * 2 + j;
                        int n = ntile * 64 + nl;
                        float val = c[mf][nf][pr * 2 + j] * sInv[nl];
                        if (n >= NCLS) val = -1e30f;
                        if (n == lbl) g_ll[R] = val;
                        v[nf * 2 + j] = val;
                        mx = fmaxf(mx, val);
                    }
                mx = fmaxf(mx, __shfl_xor_sync(0xffffffffu, mx, 1));
                mx = fmaxf(mx, __shfl_xor_sync(0xffffffffu, mx, 2));
                float s = 0.f;
                #pragma unroll
                for (int i = 0; i < 8; i++) s += __expf(v[i] - mx);
                s += __shfl_xor_sync(0xffffffffu, s, 1);
                s += __shfl_xor_sync(0xffffffffu, s, 2);
                if (tg == 0) {
                    int chunk = ntile * 2 + wn;
                    g_pmax[chunk * ROWS2 + R] = mx;
                    g_psum[chunk * ROWS2 + R] = s;
                }
            }
    } else {
        // ================= gemm2: bf16 sim + soft-margin =================
        int bid2 = blockIdx.x;
        int ntile2 = bid2 & 15, mtile2 = bid2 >> 4;   // 16 x 16
        int wm = warp & 1, wn = warp >> 1;            // 2 x 4 warps
        float c[2][2][4];
        #pragma unroll
        for (int mf = 0; mf < 2; mf++)
            #pragma unroll
            for (int nf = 0; nf < 2; nf++)
                #pragma unroll
                for (int j = 0; j < 4; j++) c[mf][nf][j] = 0.f;

        const uint8_t* ab8 = (const uint8_t*)g_abuf;
        uint32_t adst0 = (uint32_t)(arow * 128) + asw;
        const uint8_t* asrc0 = ab8 + ((size_t)(mtile2 * 64 + arow)) * (FEAT * 2) + q * 16;
        uint32_t bdst0 = (uint32_t)F8_BB + (uint32_t)(arow * 128) + asw;
        const uint8_t* bsrc0 = ab8 + ((size_t)(BATCH + ntile2 * 64 + arow)) * (FEAT * 2) + q * 16;

        int koff = 0;
        auto issue_stage2 = [&](uint32_t bufbase) {
            #pragma unroll
            for (int i = 0; i < 2; i++)
                cpa16(bufbase + adst0 + i * 4096, asrc0 + (size_t)i * 32 * (FEAT * 2) + koff);
            #pragma unroll
            for (int i = 0; i < 2; i++)
                cpa16(bufbase + bdst0 + i * 4096, bsrc0 + (size_t)i * 32 * (FEAT * 2) + koff);
            cpa_commit();
            koff += 128;
        };

        int arow0 = wm * 32 + (lane & 15);
        int brow0 = wn * 16 + (lane & 7) + ((lane >> 4) << 3);
        int ahi = lane >> 4, bhi = (lane >> 3) & 1;
        uint32_t aoff = (uint32_t)(arow0 * 128);
        uint32_t boff = (uint32_t)F8_BB + (uint32_t)(brow0 * 128);
        uint32_t colA[4], colB[4];
        #pragma unroll
        for (int ks = 0; ks < 4; ks++) {
            colA[ks] = (uint32_t)(((ks * 2 + ahi) ^ (arow0 & 7)) << 4);
            colB[ks] = (uint32_t)(((ks * 2 + bhi) ^ (brow0 & 7)) << 4);
        }

        issue_stage2(sb);
        issue_stage2(sb + F8_STG);

        for (int kt = 0; kt < G2_NSTG; kt++) {
            uint32_t bufbase = sb + (kt % 3) * F8_STG;
            if (kt < G2_NSTG - 1) cpa_wait<1>(); else cpa_wait<0>();
            __syncthreads();
            if (kt + 2 < G2_NSTG) issue_stage2(sb + ((kt + 2) % 3) * F8_STG);

            uint32_t abase = bufbase + aoff;
            uint32_t bbase = bufbase + boff;
            #pragma unroll
            for (int ks = 0; ks < 4; ks++) {
                uint32_t a[2][4], b[2][2];
                ldmx4(a[0], abase + colA[ks]);
                ldmx4(a[1], abase + 2048 + colA[ks]);
                {
                    uint32_t r[4];
                    ldmx4(r, bbase + colB[ks]);
                    b[0][0] = r[0]; b[0][1] = r[1];
                    b[1][0] = r[2]; b[1][1] = r[3];
                }
                #pragma unroll
                for (int mf = 0; mf < 2; mf++)
                    #pragma unroll
                    for (int nf = 0; nf < 2; nf++)
                        mma16816(c[mf][nf], a[mf], b[nf]);
            }
        }

        int g = lane >> 2, tg = lane & 3;
        float local = 0.f;
        #pragma unroll
        for (int mf = 0; mf < 2; mf++)
            #pragma unroll
            for (int pr = 0; pr < 2; pr++) {
                int R = mtile2 * 64 + wm * 32 + mf * 16 + pr * 8 + g;
                int lr = g_lab[R];
                #pragma unroll
                for (int nf = 0; nf < 2; nf++)
                    #pragma unroll
                    for (int j = 0; j < 2; j++) {
                        int n = ntile2 * 64 + wn * 16 + nf * 8 + tg * 2 + j;
                        int lc = g_lab[n];
                        float s = c[mf][nf][pr * 2 + j];
                        float x = (lr == lc) ? (-10.f * (s - 0.6f))
                                             : (40.f * (s - 0.4f));
                        local += (x > 15.f) ? x : log1pf(__expf(x));
                    }
            }
        #pragma unroll
        for (int o = 16; o > 0; o >>= 1) local += __shfl_xor_sync(0xffffffffu, local, o);
        if (lane == 0) sInv[warp] = local;      // reuse sInv as scratch
        __syncthreads();
        if (tid == 0) {
            float t2 = 0.f;
            #pragma unroll
            for (int i = 0; i < 8; i++) t2 += sInv[i];
            g_gal_part[bid2] = t2;
        }
    }
}

// ---------------- combine + finalize (last-block pattern) ----------------
__global__ void combine_final_kernel(float* __restrict__ out) {
    int r = blockIdx.x * 64 + threadIdx.x;
    float mx = -1e30f;
    #pragma unroll 8
    for (int i = 0; i < NCH; i++) mx = fmaxf(mx, g_pmax[i * ROWS2 + r]);
    float s = 0.f;
    #pragma unroll 8
    for (int i = 0; i < NCH; i++)
        s += g_psum[i * ROWS2 + r] * __expf(g_pmax[i * ROWS2 + r] - mx);
    float contrib = mx + logf(s) - g_ll[r];

    int lane = threadIdx.x & 31, wid = threadIdx.x >> 5;
    #pragma unroll
    for (int o = 16; o > 0; o >>= 1) contrib += __shfl_xor_sync(0xffffffffu, contrib, o);
    __shared__ float ws[2];
    __shared__ int s_ticket;
    if (lane == 0) ws[wid] = contrib;
    __syncthreads();
    if (threadIdx.x == 0) {
        g_inst_part[blockIdx.x] = ws[0] + ws[1];
        __threadfence();
        s_ticket = atomicAdd(&g_ctr, 1);
    }
    __syncthreads();
    if (s_ticket == 31) {
        // last block: all 32 g_inst_part entries visible; fixed-order sums
        if (threadIdx.x == 0) {
            float si = 0.f;
            for (int i = 0; i < 32; i++) si += g_inst_part[i];
            float sg = 0.f;
            for (int i = 0; i < G2_BLOCKS; i++) sg += g_gal_part[i];
            out[0] = si * (1.0f / BATCH);
            out[1] = 2.0f * sg / BATCH;
            g_ctr = 0;                   // reset for next graph replay
        }
    }
}

// ---------------- launch: 3 kernels, one stream ----------------
extern "C" void kernel_launch(void* const* d_in, const int* in_sizes, int n_in,
                              void* d_out, int out_size) {
    const float* vis = (const float*)d_in[0];
    const float* txt = (const float*)d_in[1];
    const int* lab = (const int*)d_in[2];
    const float* W = (const float*)d_in[3];
    float* out = (float*)d_out;

    cudaFuncSetAttribute(gemm_fused_kernel,
                         cudaFuncAttributeMaxDynamicSharedMemorySize, G1_SMEM);

    prep_fused_kernel<<<WT_BLOCKS + ROWS2, 256>>>(W, vis, txt, lab);
    gemm_fused_kernel<<<G1_BLOCKS + G2_BLOCKS, 256, G1_SMEM>>>();
    combine_final_kernel<<<32, 64>>>(out);
}

// round 14
// speedup vs baseline: 1.0387x; 1.0372x over previous
#include <cuda_runtime.h>
#include <cuda_bf16.h>
#include <cuda_fp8.h>
#include <math.h>
#include <stdint.h>

#define BATCH 1024
#define FEAT  2048
#define NCLS  11003
#define NPAD  11008
#define NT1   172           // N tiles of 64 for gemm1
#define NCH   344           // 32-col LSE chunks (NPAD/32)
#define ROWS2 2048          // stacked [v; t]

#define ASCALE 64.0f
#define WSCALE 4.0f
#define DESCALE2 (1.0f / (ASCALE * ASCALE))   // gemm2 sim descale

#define WT_BLOCKS (344 * 16)            // wtrans sub-grid
#define G1_BLOCKS (NT1 * 16)            // 2752
#define G2_BLOCKS 128                   // gemm2 128x64 tiles (8 m x 16 n)

// ---------------- device scratch (static, no runtime alloc) ----------------
__device__ __align__(128) uint8_t g_a8[(size_t)ROWS2 * FEAT];   // fp8 [v-hat;t-hat] * 64
__device__ __align__(128) uint8_t g_w8t[(size_t)NPAD * FEAT];   // fp8 W^T [n][k] * 4
__device__ float g_colsqp[16 * NPAD];
__device__ float g_ll[ROWS2];
__device__ float g_pmax[NCH * ROWS2];
__device__ float g_psum[NCH * ROWS2];
__device__ float g_gal_part[G2_BLOCKS];
__device__ float g_inst_part[32];
__device__ int   g_lab[BATCH];
__device__ int   g_ctr;                 // zero-init; self-resetting ticket

__device__ __forceinline__ uint8_t to_e4m3(float x) {
    __nv_fp8_e4m3 v(x);
    return *reinterpret_cast<uint8_t*>(&v);
}

// ======================= prep_fused: wtrans + normalize =======================
__global__ void prep_fused_kernel(const float* __restrict__ W,
                                  const float* __restrict__ vis,
                                  const float* __restrict__ txt,
                                  const int* __restrict__ lb) {
    __shared__ float s[128][33];
    __shared__ float sq[8][33];
    int bid = blockIdx.x;
    int t = threadIdx.x;

    if (bid < WT_BLOCKS) {
        // ---- wtrans: W -> fp8 [n][k] + colsq partials ----
        int tx = t & 31, ty = t >> 5;
        int c0 = (bid % 344) * 32, k0 = (bid / 344) * 128;
        int c = c0 + tx;
        float p = 0.f;
        #pragma unroll
        for (int i = 0; i < 16; i++) {
            int k = k0 + ty + 8 * i;
            float w = (c < NCLS) ? W[(size_t)k * NCLS + c] : 0.f;
            s[ty + 8 * i][tx] = w;
            p += w * w;
        }
        sq[ty][tx] = p;
        __syncthreads();
        if (ty == 0) {
            float ssum = 0.f;
            #pragma unroll
            for (int i = 0; i < 8; i++) ssum += sq[i][tx];
            g_colsqp[(bid / 344) * NPAD + c] = ssum;
        }
        #pragma unroll
        for (int j = 0; j < 4; j++) {
            int nl = ty + 8 * j;
            int kq = tx;
            uchar4 pk = make_uchar4(to_e4m3(s[4*kq+0][nl] * WSCALE),
                                    to_e4m3(s[4*kq+1][nl] * WSCALE),
                                    to_e4m3(s[4*kq+2][nl] * WSCALE),
                                    to_e4m3(s[4*kq+3][nl] * WSCALE));
            *(uint32_t*)(g_w8t + (size_t)(c0 + nl) * FEAT + k0 + 4 * kq) =
                *reinterpret_cast<uint32_t*>(&pk);
        }
    } else {
        // ---- normalize row r -> fp8 only; block WT_BLOCKS also loads labels ----
        int r = bid - WT_BLOCKS;        // 0..2047
        if (r == 0) {
            bool is64 = true;
            #pragma unroll
            for (int j = 1; j < 64; j += 2)
                if (lb[j] != 0) is64 = false;
            #pragma unroll
            for (int i = 0; i < 4; i++) {
                int idx = t + 256 * i;
                g_lab[idx] = is64 ? lb[2 * idx] : lb[idx];
            }
        }
        const float* src = (r < BATCH) ? (vis + (size_t)r * FEAT)
                                       : (txt + (size_t)(r - BATCH) * FEAT);
        float4 x0 = ((const float4*)src)[t];
        float4 x1 = ((const float4*)src)[t + 256];
        float ss = x0.x*x0.x + x0.y*x0.y + x0.z*x0.z + x0.w*x0.w
                 + x1.x*x1.x + x1.y*x1.y + x1.z*x1.z + x1.w*x1.w;
        #pragma unroll
        for (int o = 16; o > 0; o >>= 1) ss += __shfl_xor_sync(0xffffffffu, ss, o);
        float* ws = &sq[0][0];
        if ((t & 31) == 0) ws[t >> 5] = ss;
        __syncthreads();
        if (t == 0) {
            float sum = 0.f;
            #pragma unroll
            for (int i = 0; i < 8; i++) sum += ws[i];
            ws[8] = rsqrtf(sum);
        }
        __syncthreads();
        float fa = ws[8] * ASCALE;
        uchar4 p0 = make_uchar4(to_e4m3(x0.x*fa), to_e4m3(x0.y*fa),
                                to_e4m3(x0.z*fa), to_e4m3(x0.w*fa));
        uchar4 p1 = make_uchar4(to_e4m3(x1.x*fa), to_e4m3(x1.y*fa),
                                to_e4m3(x1.z*fa), to_e4m3(x1.w*fa));
        uint32_t* d8 = (uint32_t*)(g_a8 + (size_t)r * FEAT);
        d8[t]       = *reinterpret_cast<uint32_t*>(&p0);
        d8[t + 256] = *reinterpret_cast<uint32_t*>(&p1);
    }
}

// ---------------- mma helpers ----------------
__device__ __forceinline__ void ldmx4(uint32_t* r, uint32_t a) {
    asm volatile("ldmatrix.sync.aligned.m8n8.x4.shared.b16 {%0,%1,%2,%3},[%4];\n"
                 : "=r"(r[0]), "=r"(r[1]), "=r"(r[2]), "=r"(r[3]) : "r"(a));
}
__device__ __forceinline__ void mma16832f8(float* c, const uint32_t* a, const uint32_t* b) {
    asm volatile("mma.sync.aligned.m16n8k32.row.col.f32.e4m3.e4m3.f32 "
                 "{%0,%1,%2,%3},{%4,%5,%6,%7},{%8,%9},{%0,%1,%2,%3};\n"
                 : "+f"(c[0]), "+f"(c[1]), "+f"(c[2]), "+f"(c[3])
                 : "r"(a[0]), "r"(a[1]), "r"(a[2]), "r"(a[3]),
                   "r"(b[0]), "r"(b[1]));
}
__device__ __forceinline__ void cpa16(uint32_t dst, const void* src) {
    asm volatile("cp.async.cg.shared.global [%0], [%1], 16;" :: "r"(dst), "l"(src));
}
__device__ __forceinline__ void cpa_commit() {
    asm volatile("cp.async.commit_group;" ::: "memory");
}
template <int N> __device__ __forceinline__ void cpa_wait() {
    asm volatile("cp.async.wait_group %0;" :: "n"(N) : "memory");
}

// ======================= shared fp8 128x64x2048 mainloop =======================
#define F8_AB   (128 * 128)             // 16384
#define F8_BB   (64 * 128)              // 8192
#define F8_STG  (F8_AB + F8_BB)         // 24576
#define G1_SMEM (3 * F8_STG)            // 73728
#define G1_NSTG 16

// A tile: 128 rows x FEAT fp8 at asrc_base; B tile: 64 rows x FEAT at bsrc_base.
// If inv_base >= 0, fills sInv[0..63] from g_colsqp during pipeline fill.
__device__ __forceinline__ void fp8_mainloop(
    const uint8_t* __restrict__ asrc_base, const uint8_t* __restrict__ bsrc_base,
    uint32_t sb, int tid, int lane, int wm, int wn,
    float* sInv, int inv_base, float c[2][4][4])
{
    #pragma unroll
    for (int mf = 0; mf < 2; mf++)
        #pragma unroll
        for (int nf = 0; nf < 4; nf++)
            #pragma unroll
            for (int j = 0; j < 4; j++) c[mf][nf][j] = 0.f;

    int arow = tid >> 3, q = tid & 7;
    uint32_t asw = (uint32_t)((q ^ (arow & 7)) << 4);
    uint32_t adst0 = (uint32_t)(arow * 128) + asw;
    const uint8_t* asrc0 = asrc_base + (size_t)arow * FEAT + q * 16;
    uint32_t bdst0 = (uint32_t)F8_AB + (uint32_t)(arow * 128) + asw;
    const uint8_t* bsrc0 = bsrc_base + (size_t)arow * FEAT + q * 16;

    int koff = 0;
    auto issue_stage = [&](uint32_t bufbase) {
        #pragma unroll
        for (int i = 0; i < 4; i++)
            cpa16(bufbase + adst0 + i * 4096, asrc0 + (size_t)i * 32 * FEAT + koff);
        #pragma unroll
        for (int i = 0; i < 2; i++)
            cpa16(bufbase + bdst0 + i * 4096, bsrc0 + (size_t)i * 32 * FEAT + koff);
        cpa_commit();
        koff += 128;
    };

    int arow0 = wm * 32 + (lane & 15);
    int brow0 = wn * 32 + (lane & 7) + ((lane >> 4) << 3);
    int ahi = lane >> 4, bhi = (lane >> 3) & 1;
    uint32_t aoff = (uint32_t)(arow0 * 128);
    uint32_t boff = (uint32_t)F8_AB + (uint32_t)(brow0 * 128);
    uint32_t colA[4], colB[4];
    #pragma unroll
    for (int ks = 0; ks < 4; ks++) {
        colA[ks] = (uint32_t)(((ks * 2 + ahi) ^ (arow0 & 7)) << 4);
        colB[ks] = (uint32_t)(((ks * 2 + bhi) ^ (brow0 & 7)) << 4);
    }

    issue_stage(sb);
    issue_stage(sb + F8_STG);

    if (inv_base >= 0 && tid < 64) {     // hidden under pipeline fill
        int cidx = inv_base + tid;
        float s = 0.f;
        #pragma unroll
        for (int i = 0; i < 16; i++) s += g_colsqp[i * NPAD + cidx];
        sInv[tid] = (cidx < NCLS) ? (28.0f / (ASCALE * WSCALE)) * rsqrtf(s) : 0.f;
    }

    for (int kt = 0; kt < G1_NSTG; kt++) {
        uint32_t bufbase = sb + (kt % 3) * F8_STG;
        if (kt < G1_NSTG - 1) cpa_wait<1>(); else cpa_wait<0>();
        __syncthreads();
        if (kt + 2 < G1_NSTG) issue_stage(sb + ((kt + 2) % 3) * F8_STG);

        uint32_t abase = bufbase + aoff;
        uint32_t bbase = bufbase + boff;
        #pragma unroll
        for (int ks = 0; ks < 4; ks++) {
            uint32_t a[2][4], b[4][2];
            ldmx4(a[0], abase + colA[ks]);
            ldmx4(a[1], abase + 2048 + colA[ks]);
            {
                uint32_t r[4];
                ldmx4(r, bbase + colB[ks]);
                b[0][0] = r[0]; b[0][1] = r[1];
                b[1][0] = r[2]; b[1][1] = r[3];
                ldmx4(r, bbase + 2048 + colB[ks]);
                b[2][0] = r[0]; b[2][1] = r[1];
                b[3][0] = r[2]; b[3][1] = r[3];
            }
            #pragma unroll
            for (int mf = 0; mf < 2; mf++)
                #pragma unroll
                for (int nf = 0; nf < 4; nf++)
                    mma16832f8(c[mf][nf], a[mf], b[nf]);
        }
    }
}

// ======================= gemm_fused =======================
// blocks [0, G1_BLOCKS): gemm1 (logits + LSE)
// blocks [G1_BLOCKS, +G2_BLOCKS): gemm2 (sim + soft-margin), identical mainloop
__global__ __launch_bounds__(256, 3) void gemm_fused_kernel() {
    extern __shared__ char smem[];
    __shared__ float sInv[64];
    int tid = threadIdx.x, warp = tid >> 5, lane = tid & 31;
    int wm = warp & 3, wn = warp >> 2;
    uint32_t sb = (uint32_t)__cvta_generic_to_shared(smem);
    float c[2][4][4];

    if (blockIdx.x < G1_BLOCKS) {
        // ================= gemm1: fp8 logits + LSE =================
        int ntile = blockIdx.x % NT1, mtile = blockIdx.x / NT1;
        fp8_mainloop(g_a8 + (size_t)(mtile * 128) * FEAT,
                     g_w8t + (size_t)(ntile * 64) * FEAT,
                     sb, tid, lane, wm, wn, sInv, ntile * 64, c);

        int g = lane >> 2, tg = lane & 3;
        #pragma unroll
        for (int mf = 0; mf < 2; mf++)
            #pragma unroll
            for (int pr = 0; pr < 2; pr++) {
                int R = mtile * 128 + wm * 32 + mf * 16 + pr * 8 + g;
                int lbl = g_lab[R & (BATCH - 1)];
                float v[8];
                float mx = -1e30f;
                #pragma unroll
                for (int nf = 0; nf < 4; nf++)
                    #pragma unroll
                    for (int j = 0; j < 2; j++) {
                        int nl = wn * 32 + nf * 8 + tg * 2 + j;
                        int n = ntile * 64 + nl;
                        float val = c[mf][nf][pr * 2 + j] * sInv[nl];
                        if (n >= NCLS) val = -1e30f;
                        if (n == lbl) g_ll[R] = val;
                        v[nf * 2 + j] = val;
                        mx = fmaxf(mx, val);
                    }
                mx = fmaxf(mx, __shfl_xor_sync(0xffffffffu, mx, 1));
                mx = fmaxf(mx, __shfl_xor_sync(0xffffffffu, mx, 2));
                float s = 0.f;
                #pragma unroll
                for (int i = 0; i < 8; i++) s += __expf(v[i] - mx);
                s += __shfl_xor_sync(0xffffffffu, s, 1);
                s += __shfl_xor_sync(0xffffffffu, s, 2);
                if (tg == 0) {
                    int chunk = ntile * 2 + wn;
                    g_pmax[chunk * ROWS2 + R] = mx;
                    g_psum[chunk * ROWS2 + R] = s;
                }
            }
    } else {
        // ================= gemm2: fp8 sim + soft-margin =================
        int bid2 = blockIdx.x - G1_BLOCKS;      // 0..127
        int ntile2 = bid2 & 15, mtile2 = bid2 >> 4;   // 16 n x 8 m
        fp8_mainloop(g_a8 + (size_t)(mtile2 * 128) * FEAT,
                     g_a8 + (size_t)(BATCH + ntile2 * 64) * FEAT,
                     sb, tid, lane, wm, wn, sInv, -1, c);

        int g = lane >> 2, tg = lane & 3;
        float local = 0.f;
        #pragma unroll
        for (int mf = 0; mf < 2; mf++)
            #pragma unroll
            for (int pr = 0; pr < 2; pr++) {
                int R = mtile2 * 128 + wm * 32 + mf * 16 + pr * 8 + g;
                int lr = g_lab[R];
                #pragma unroll
                for (int nf = 0; nf < 4; nf++)
                    #pragma unroll
                    for (int j = 0; j < 2; j++) {
                        int n = ntile2 * 64 + wn * 32 + nf * 8 + tg * 2 + j;
                        int lc = g_lab[n];
                        float s = c[mf][nf][pr * 2 + j] * DESCALE2;
                        float x = (lr == lc) ? (-10.f * (s - 0.6f))
                                             : (40.f * (s - 0.4f));
                        local += (x > 15.f) ? x : log1pf(__expf(x));
                    }
            }
        #pragma unroll
        for (int o = 16; o > 0; o >>= 1) local += __shfl_xor_sync(0xffffffffu, local, o);
        if (lane == 0) sInv[warp] = local;      // reuse sInv as scratch
        __syncthreads();
        if (tid == 0) {
            float t2 = 0.f;
            #pragma unroll
            for (int i = 0; i < 8; i++) t2 += sInv[i];
            g_gal_part[bid2] = t2;
        }
    }
}

// ---------------- combine + finalize (last-block pattern) ----------------
__global__ void combine_final_kernel(float* __restrict__ out) {
    int r = blockIdx.x * 64 + threadIdx.x;
    float mx = -1e30f;
    #pragma unroll 8
    for (int i = 0; i < NCH; i++) mx = fmaxf(mx, g_pmax[i * ROWS2 + r]);
    float s = 0.f;
    #pragma unroll 8
    for (int i = 0; i < NCH; i++)
        s += g_psum[i * ROWS2 + r] * __expf(g_pmax[i * ROWS2 + r] - mx);
    float contrib = mx + logf(s) - g_ll[r];

    int lane = threadIdx.x & 31, wid = threadIdx.x >> 5;
    #pragma unroll
    for (int o = 16; o > 0; o >>= 1) contrib += __shfl_xor_sync(0xffffffffu, contrib, o);
    __shared__ float ws[2];
    __shared__ int s_ticket;
    if (lane == 0) ws[wid] = contrib;
    __syncthreads();
    if (threadIdx.x == 0) {
        g_inst_part[blockIdx.x] = ws[0] + ws[1];
        __threadfence();
        s_ticket = atomicAdd(&g_ctr, 1);
    }
    __syncthreads();
    if (s_ticket == 31) {
        if (threadIdx.x == 0) {
            float si = 0.f;
            for (int i = 0; i < 32; i++) si += g_inst_part[i];
            float sg = 0.f;
            for (int i = 0; i < G2_BLOCKS; i++) sg += g_gal_part[i];
            out[0] = si * (1.0f / BATCH);
            out[1] = 2.0f * sg / BATCH;
            g_ctr = 0;                   // reset for next graph replay
        }
    }
}

// ---------------- launch: 3 kernels, one stream ----------------
extern "C" void kernel_launch(void* const* d_in, const int* in_sizes, int n_in,
                              void* d_out, int out_size) {
    const float* vis = (const float*)d_in[0];
    const float* txt = (const float*)d_in[1];
    const int* lab = (const int*)d_in[2];
    const float* W = (const float*)d_in[3];
    float* out = (float*)d_out;

    cudaFuncSetAttribute(gemm_fused_kernel,
                         cudaFuncAttributeMaxDynamicSharedMemorySize, G1_SMEM);

    prep_fused_kernel<<<WT_BLOCKS + ROWS2, 256>>>(W, vis, txt, lab);
    gemm_fused_kernel<<<G1_BLOCKS + G2_BLOCKS, 256, G1_SMEM>>>();
    combine_final_kernel<<<32, 64>>>(out);
}

// round 15
// speedup vs baseline: 1.1139x; 1.0724x over previous
#include <cuda_runtime.h>
#include <cuda_bf16.h>
#include <cuda_fp8.h>
#include <math.h>
#include <stdint.h>

#define BATCH 1024
#define FEAT  2048
#define NCLS  11003
#define NPAD  11008
#define NT1   172           // N tiles of 64 for gemm1
#define NCH   344           // 32-col LSE chunks (NPAD/32)
#define ROWS2 2048          // stacked [v; t]

#define ASCALE 64.0f
#define WSCALE 4.0f
#define DESCALE2 (1.0f / (ASCALE * ASCALE))   // gemm2 sim descale
#define LSE_MAX 28.0f                         // |logit| <= 28 always

#define WT_BLOCKS (344 * 16)            // wtrans sub-grid
#define G1F_BLOCKS 2536                 // full gemm1 tiles (mtile*172+ntile < 2536)
#define G2_BLOCKS  128                  // gemm2 128x64 tiles (8 m x 16 n)
#define HALF_BLOCKS 432                 // 216 split gemm1 tiles x 2 halves
#define TOT_BLOCKS (G1F_BLOCKS + G2_BLOCKS + HALF_BLOCKS)   // 3096

// ---------------- device scratch (static, no runtime alloc) ----------------
__device__ __align__(128) uint8_t g_a8[(size_t)ROWS2 * FEAT];   // fp8 [v-hat;t-hat] * 64
__device__ __align__(128) uint8_t g_w8t[(size_t)NPAD * FEAT];   // fp8 W^T [n][k] * 4
__device__ float g_colsqp[16 * NPAD];
__device__ float g_ll[ROWS2];
__device__ float g_psum[NCH * ROWS2];   // chunkwise sum exp(v - 28)
__device__ float g_gal_part[G2_BLOCKS];
__device__ float g_inst_part[32];
__device__ int   g_lab[BATCH];
__device__ int   g_ctr;                 // zero-init; self-resetting ticket

__device__ __forceinline__ uint8_t to_e4m3(float x) {
    __nv_fp8_e4m3 v(x);
    return *reinterpret_cast<uint8_t*>(&v);
}

// ======================= prep_fused: wtrans + normalize =======================
__global__ void prep_fused_kernel(const float* __restrict__ W,
                                  const float* __restrict__ vis,
                                  const float* __restrict__ txt,
                                  const int* __restrict__ lb) {
    __shared__ float s[128][33];
    __shared__ float sq[8][33];
    int bid = blockIdx.x;
    int t = threadIdx.x;

    if (bid < WT_BLOCKS) {
        // ---- wtrans: W -> fp8 [n][k] + colsq partials ----
        int tx = t & 31, ty = t >> 5;
        int c0 = (bid % 344) * 32, k0 = (bid / 344) * 128;
        int c = c0 + tx;
        float p = 0.f;
        #pragma unroll
        for (int i = 0; i < 16; i++) {
            int k = k0 + ty + 8 * i;
            float w = (c < NCLS) ? W[(size_t)k * NCLS + c] : 0.f;
            s[ty + 8 * i][tx] = w;
            p += w * w;
        }
        sq[ty][tx] = p;
        __syncthreads();
        if (ty == 0) {
            float ssum = 0.f;
            #pragma unroll
            for (int i = 0; i < 8; i++) ssum += sq[i][tx];
            g_colsqp[(bid / 344) * NPAD + c] = ssum;
        }
        #pragma unroll
        for (int j = 0; j < 4; j++) {
            int nl = ty + 8 * j;
            int kq = tx;
            uchar4 pk = make_uchar4(to_e4m3(s[4*kq+0][nl] * WSCALE),
                                    to_e4m3(s[4*kq+1][nl] * WSCALE),
                                    to_e4m3(s[4*kq+2][nl] * WSCALE),
                                    to_e4m3(s[4*kq+3][nl] * WSCALE));
            *(uint32_t*)(g_w8t + (size_t)(c0 + nl) * FEAT + k0 + 4 * kq) =
                *reinterpret_cast<uint32_t*>(&pk);
        }
    } else {
        // ---- normalize row r -> fp8; block WT_BLOCKS also loads labels ----
        int r = bid - WT_BLOCKS;        // 0..2047
        if (r == 0) {
            bool is64 = true;
            #pragma unroll
            for (int j = 1; j < 64; j += 2)
                if (lb[j] != 0) is64 = false;
            #pragma unroll
            for (int i = 0; i < 4; i++) {
                int idx = t + 256 * i;
                g_lab[idx] = is64 ? lb[2 * idx] : lb[idx];
            }
        }
        const float* src = (r < BATCH) ? (vis + (size_t)r * FEAT)
                                       : (txt + (size_t)(r - BATCH) * FEAT);
        float4 x0 = ((const float4*)src)[t];
        float4 x1 = ((const float4*)src)[t + 256];
        float ss = x0.x*x0.x + x0.y*x0.y + x0.z*x0.z + x0.w*x0.w
                 + x1.x*x1.x + x1.y*x1.y + x1.z*x1.z + x1.w*x1.w;
        #pragma unroll
        for (int o = 16; o > 0; o >>= 1) ss += __shfl_xor_sync(0xffffffffu, ss, o);
        float* ws = &sq[0][0];
        if ((t & 31) == 0) ws[t >> 5] = ss;
        __syncthreads();
        if (t == 0) {
            float sum = 0.f;
            #pragma unroll
            for (int i = 0; i < 8; i++) sum += ws[i];
            ws[8] = rsqrtf(sum);
        }
        __syncthreads();
        float fa = ws[8] * ASCALE;
        uchar4 p0 = make_uchar4(to_e4m3(x0.x*fa), to_e4m3(x0.y*fa),
                                to_e4m3(x0.z*fa), to_e4m3(x0.w*fa));
        uchar4 p1 = make_uchar4(to_e4m3(x1.x*fa), to_e4m3(x1.y*fa),
                                to_e4m3(x1.z*fa), to_e4m3(x1.w*fa));
        uint32_t* d8 = (uint32_t*)(g_a8 + (size_t)r * FEAT);
        d8[t]       = *reinterpret_cast<uint32_t*>(&p0);
        d8[t + 256] = *reinterpret_cast<uint32_t*>(&p1);
    }
}

// ---------------- mma helpers ----------------
__device__ __forceinline__ void ldmx4(uint32_t* r, uint32_t a) {
    asm volatile("ldmatrix.sync.aligned.m8n8.x4.shared.b16 {%0,%1,%2,%3},[%4];\n"
                 : "=r"(r[0]), "=r"(r[1]), "=r"(r[2]), "=r"(r[3]) : "r"(a));
}
__device__ __forceinline__ void mma16832f8(float* c, const uint32_t* a, const uint32_t* b) {
    asm volatile("mma.sync.aligned.m16n8k32.row.col.f32.e4m3.e4m3.f32 "
                 "{%0,%1,%2,%3},{%4,%5,%6,%7},{%8,%9},{%0,%1,%2,%3};\n"
                 : "+f"(c[0]), "+f"(c[1]), "+f"(c[2]), "+f"(c[3])
                 : "r"(a[0]), "r"(a[1]), "r"(a[2]), "r"(a[3]),
                   "r"(b[0]), "r"(b[1]));
}
__device__ __forceinline__ void cpa16(uint32_t dst, const void* src) {
    asm volatile("cp.async.cg.shared.global [%0], [%1], 16;" :: "r"(dst), "l"(src));
}
__device__ __forceinline__ void cpa_commit() {
    asm volatile("cp.async.commit_group;" ::: "memory");
}
template <int N> __device__ __forceinline__ void cpa_wait() {
    asm volatile("cp.async.wait_group %0;" :: "n"(N) : "memory");
}

// ======================= shared fp8 (MF*64)x64x2048 mainloop =======================
// MF=2: 128-row tile (full). MF=1: 64-row tile (half-duration tail filler).
#define F8_BB   8192
#define G1_SMEM (3 * (128 * 128 + F8_BB))   // 73728 (worst case MF=2)
#define G1_NSTG 16

template <int MF>
__device__ __forceinline__ void fp8_mainloop(
    const uint8_t* __restrict__ asrc_base, const uint8_t* __restrict__ bsrc_base,
    uint32_t sb, int tid, int lane, int wm, int wn,
    float* sInv, int inv_base, float c[2][4][4])
{
    constexpr int AB  = MF * 64 * 128;
    constexpr int STG = AB + F8_BB;

    #pragma unroll
    for (int mf = 0; mf < MF; mf++)
        #pragma unroll
        for (int nf = 0; nf < 4; nf++)
            #pragma unroll
            for (int j = 0; j < 4; j++) c[mf][nf][j] = 0.f;

    int arow = tid >> 3, q = tid & 7;
    uint32_t asw = (uint32_t)((q ^ (arow & 7)) << 4);
    uint32_t adst0 = (uint32_t)(arow * 128) + asw;
    const uint8_t* asrc0 = asrc_base + (size_t)arow * FEAT + q * 16;
    uint32_t bdst0 = (uint32_t)AB + (uint32_t)(arow * 128) + asw;
    const uint8_t* bsrc0 = bsrc_base + (size_t)arow * FEAT + q * 16;

    int koff = 0;
    auto issue_stage = [&](uint32_t bufbase) {
        #pragma unroll
        for (int i = 0; i < 2 * MF; i++)
            cpa16(bufbase + adst0 + i * 4096, asrc0 + (size_t)i * 32 * FEAT + koff);
        #pragma unroll
        for (int i = 0; i < 2; i++)
            cpa16(bufbase + bdst0 + i * 4096, bsrc0 + (size_t)i * 32 * FEAT + koff);
        cpa_commit();
        koff += 128;
    };

    int arow0 = wm * (16 * MF) + (lane & 15);
    int brow0 = wn * 32 + (lane & 7) + ((lane >> 4) << 3);
    int ahi = lane >> 4, bhi = (lane >> 3) & 1;
    uint32_t aoff = (uint32_t)(arow0 * 128);
    uint32_t boff = (uint32_t)AB + (uint32_t)(brow0 * 128);
    uint32_t colA[4], colB[4];
    #pragma unroll
    for (int ks = 0; ks < 4; ks++) {
        colA[ks] = (uint32_t)(((ks * 2 + ahi) ^ (arow0 & 7)) << 4);
        colB[ks] = (uint32_t)(((ks * 2 + bhi) ^ (brow0 & 7)) << 4);
    }

    issue_stage(sb);
    issue_stage(sb + STG);

    if (inv_base >= 0 && tid < 64) {     // hidden under pipeline fill
        int cidx = inv_base + tid;
        float s = 0.f;
        #pragma unroll
        for (int i = 0; i < 16; i++) s += g_colsqp[i * NPAD + cidx];
        sInv[tid] = (cidx < NCLS) ? (28.0f / (ASCALE * WSCALE)) * rsqrtf(s) : 0.f;
    }

    for (int kt = 0; kt < G1_NSTG; kt++) {
        uint32_t bufbase = sb + (kt % 3) * STG;
        if (kt < G1_NSTG - 1) cpa_wait<1>(); else cpa_wait<0>();
        __syncthreads();
        if (kt + 2 < G1_NSTG) issue_stage(sb + ((kt + 2) % 3) * STG);

        uint32_t abase = bufbase + aoff;
        uint32_t bbase = bufbase + boff;
        #pragma unroll
        for (int ks = 0; ks < 4; ks++) {
            uint32_t a[2][4], b[4][2];
            #pragma unroll
            for (int mf = 0; mf < MF; mf++)
                ldmx4(a[mf], abase + mf * 2048 + colA[ks]);
            {
                uint32_t r[4];
                ldmx4(r, bbase + colB[ks]);
                b[0][0] = r[0]; b[0][1] = r[1];
                b[1][0] = r[2]; b[1][1] = r[3];
                ldmx4(r, bbase + 2048 + colB[ks]);
                b[2][0] = r[0]; b[2][1] = r[1];
                b[3][0] = r[2]; b[3][1] = r[3];
            }
            #pragma unroll
            for (int mf = 0; mf < MF; mf++)
                #pragma unroll
                for (int nf = 0; nf < 4; nf++)
                    mma16832f8(c[mf][nf], a[mf], b[nf]);
        }
    }
}

// gemm1 epilogue: fixed-max (28) chunkwise sum-exp
template <int MF>
__device__ __forceinline__ void g1_epilogue(int rowbase, int ntile,
                                            float c[2][4][4], const float* sInv,
                                            int lane, int wm, int wn)
{
    int g = lane >> 2, tg = lane & 3;
    #pragma unroll
    for (int mf = 0; mf < MF; mf++)
        #pragma unroll
        for (int pr = 0; pr < 2; pr++) {
            int R = rowbase + wm * (16 * MF) + mf * 16 + pr * 8 + g;
            int lbl = g_lab[R & (BATCH - 1)];
            float s = 0.f;
            #pragma unroll
            for (int nf = 0; nf < 4; nf++)
                #pragma unroll
                for (int j = 0; j < 2; j++) {
                    int nl = wn * 32 + nf * 8 + tg * 2 + j;
                    int n = ntile * 64 + nl;
                    float val = c[mf][nf][pr * 2 + j] * sInv[nl];
                    if (n >= NCLS) val = -1e30f;
                    if (n == lbl) g_ll[R] = val;
                    s += __expf(val - LSE_MAX);
                }
            s += __shfl_xor_sync(0xffffffffu, s, 1);
            s += __shfl_xor_sync(0xffffffffu, s, 2);
            if (tg == 0) {
                int chunk = ntile * 2 + wn;
                g_psum[chunk * ROWS2 + R] = s;
            }
        }
}

// ======================= gemm_fused =======================
// [0, 2536): gemm1 full 128-row tiles   (6 clean waves with gemm2: 2664 = 6*444)
// [2536, 2664): gemm2 128x64 tiles      (same duration as gemm1 fulls)
// [2664, 3096): gemm1 half 64-row tiles (T/2 duration -> packs the tail wave)
__global__ __launch_bounds__(256, 3) void gemm_fused_kernel() {
    extern __shared__ char smem[];
    __shared__ float sInv[64];
    int tid = threadIdx.x, warp = tid >> 5, lane = tid & 31;
    int wm = warp & 3, wn = warp >> 2;
    uint32_t sb = (uint32_t)__cvta_generic_to_shared(smem);
    float c[2][4][4];
    int bid = blockIdx.x;

    if (bid < G1F_BLOCKS) {
        // ---- gemm1 full tile ----
        int mtile = bid / NT1, ntile = bid % NT1;
        fp8_mainloop<2>(g_a8 + (size_t)(mtile * 128) * FEAT,
                        g_w8t + (size_t)(ntile * 64) * FEAT,
                        sb, tid, lane, wm, wn, sInv, ntile * 64, c);
        g1_epilogue<2>(mtile * 128, ntile, c, sInv, lane, wm, wn);
    } else if (bid < G1F_BLOCKS + G2_BLOCKS) {
        // ---- gemm2: fp8 sim + soft-margin ----
        int bid2 = bid - G1F_BLOCKS;            // 0..127
        int ntile2 = bid2 & 15, mtile2 = bid2 >> 4;   // 16 n x 8 m
        fp8_mainloop<2>(g_a8 + (size_t)(mtile2 * 128) * FEAT,
                        g_a8 + (size_t)(BATCH + ntile2 * 64) * FEAT,
                        sb, tid, lane, wm, wn, sInv, -1, c);

        int g = lane >> 2, tg = lane & 3;
        float local = 0.f;
        #pragma unroll
        for (int mf = 0; mf < 2; mf++)
            #pragma unroll
            for (int pr = 0; pr < 2; pr++) {
                int R = mtile2 * 128 + wm * 32 + mf * 16 + pr * 8 + g;
                int lr = g_lab[R];
                #pragma unroll
                for (int nf = 0; nf < 4; nf++)
                    #pragma unroll
                    for (int j = 0; j < 2; j++) {
                        int n = ntile2 * 64 + wn * 32 + nf * 8 + tg * 2 + j;
                        int lc = g_lab[n];
                        float s = c[mf][nf][pr * 2 + j] * DESCALE2;
                        float x = (lr == lc) ? (-10.f * (s - 0.6f))
                                             : (40.f * (s - 0.4f));
                        local += (x > 15.f) ? x : log1pf(__expf(x));
                    }
            }
        #pragma unroll
        for (int o = 16; o > 0; o >>= 1) local += __shfl_xor_sync(0xffffffffu, local, o);
        if (lane == 0) sInv[warp] = local;      // reuse sInv as scratch
        __syncthreads();
        if (tid == 0) {
            float t2 = 0.f;
            #pragma unroll
            for (int i = 0; i < 8; i++) t2 += sInv[i];
            g_gal_part[bid2] = t2;
        }
    } else {
        // ---- gemm1 half tile (64 rows) ----
        int h = bid - (G1F_BLOCKS + G2_BLOCKS);       // 0..431
        int gt = G1F_BLOCKS + (h >> 1);               // global tile 2536..2751
        int mtile = gt / NT1, ntile = gt % NT1;
        int half = h & 1;
        fp8_mainloop<1>(g_a8 + (size_t)(mtile * 128 + half * 64) * FEAT,
                        g_w8t + (size_t)(ntile * 64) * FEAT,
                        sb, tid, lane, wm, wn, sInv, ntile * 64, c);
        g1_epilogue<1>(mtile * 128 + half * 64, ntile, c, sInv, lane, wm, wn);
    }
}

// ---------------- combine + finalize (fixed-max LSE; last-block pattern) ----------------
__global__ void combine_final_kernel(float* __restrict__ out) {
    int r = blockIdx.x * 64 + threadIdx.x;
    float s = 0.f;
    #pragma unroll 8
    for (int i = 0; i < NCH; i++) s += g_psum[i * ROWS2 + r];
    float contrib = LSE_MAX + logf(s) - g_ll[r];

    int lane = threadIdx.x & 31, wid = threadIdx.x >> 5;
    #pragma unroll
    for (int o = 16; o > 0; o >>= 1) contrib += __shfl_xor_sync(0xffffffffu, contrib, o);
    __shared__ float ws[2];
    __shared__ int s_ticket;
    if (lane == 0) ws[wid] = contrib;
    __syncthreads();
    if (threadIdx.x == 0) {
        g_inst_part[blockIdx.x] = ws[0] + ws[1];
        __threadfence();
        s_ticket = atomicAdd(&g_ctr, 1);
    }
    __syncthreads();
    if (s_ticket == 31) {
        if (threadIdx.x == 0) {
            float si = 0.f;
            for (int i = 0; i < 32; i++) si += g_inst_part[i];
            float sg = 0.f;
            for (int i = 0; i < G2_BLOCKS; i++) sg += g_gal_part[i];
            out[0] = si * (1.0f / BATCH);
            out[1] = 2.0f * sg / BATCH;
            g_ctr = 0;                   // reset for next graph replay
        }
    }
}

// ---------------- launch: 3 kernels, one stream ----------------
extern "C" void kernel_launch(void* const* d_in, const int* in_sizes, int n_in,
                              void* d_out, int out_size) {
    const float* vis = (const float*)d_in[0];
    const float* txt = (const float*)d_in[1];
    const int* lab = (const int*)d_in[2];
    const float* W = (const float*)d_in[3];
    float* out = (float*)d_out;

    cudaFuncSetAttribute(gemm_fused_kernel,
                         cudaFuncAttributeMaxDynamicSharedMemorySize, G1_SMEM);

    prep_fused_kernel<<<WT_BLOCKS + ROWS2, 256>>>(W, vis, txt, lab);
    gemm_fused_kernel<<<TOT_BLOCKS, 256, G1_SMEM>>>();
    combine_final_kernel<<<32, 64>>>(out);
}